// round 12
// baseline (speedup 1.0000x reference)
#include <cuda_runtime.h>
#include <cuda_fp16.h>
#include <cstdint>
#include <math.h>

#define N_NODES 50000
#define N_EDGES 800000
#define FDIM    128
#define RNUM    11
#define NLAYER  2
#define NTILES  391                              // ceil(50000/128)
#define SCALE2F (0.17677669529663687f * 1.4426950408889634f)   // (1/sqrt32)*log2(e)

typedef unsigned long long ull;

// ---------------- scratch (device globals; no allocation allowed) -------------
__device__ float  g_h[N_NODES * FDIM];
__device__ float  g_q[N_NODES * FDIM];
__device__ __align__(16) __half g_kvh[N_NODES * 2 * FDIM]; // per node: 128 k, 128 v
__device__ __align__(16) __half g_wh[6 * FDIM * FDIM];     // fp16 W, [layer*3+sel][k][n]
__device__ float  g_rel[NLAYER * RNUM * FDIM];
__device__ int    g_rowptr[N_NODES + 1];
__device__ int    g_cursor[N_NODES];
__device__ int    g_epack[N_EDGES];              // src | (edge_type << 20)

// ---------------- PTX helpers --------------------------------------------------
__device__ __forceinline__ unsigned smem_u32(const void* p) {
    unsigned a;
    asm("{ .reg .u64 t; cvta.to.shared.u64 t, %1; cvt.u32.u64 %0, t; }" : "=r"(a) : "l"(p));
    return a;
}
__device__ __forceinline__ void ldsm4(unsigned* r, unsigned addr) {
    asm volatile("ldmatrix.sync.aligned.m8n8.x4.shared.b16 {%0,%1,%2,%3}, [%4];"
                 : "=r"(r[0]), "=r"(r[1]), "=r"(r[2]), "=r"(r[3]) : "r"(addr));
}
__device__ __forceinline__ void ldsm4t(unsigned* r, unsigned addr) {
    asm volatile("ldmatrix.sync.aligned.m8n8.x4.trans.shared.b16 {%0,%1,%2,%3}, [%4];"
                 : "=r"(r[0]), "=r"(r[1]), "=r"(r[2]), "=r"(r[3]) : "r"(addr));
}
__device__ __forceinline__ void mma16816(float* d, const unsigned* a, const unsigned* b) {
    asm volatile(
        "mma.sync.aligned.m16n8k16.row.col.f32.f16.f16.f32 "
        "{%0,%1,%2,%3}, {%4,%5,%6,%7}, {%8,%9}, {%0,%1,%2,%3};"
        : "+f"(d[0]), "+f"(d[1]), "+f"(d[2]), "+f"(d[3])
        : "r"(a[0]), "r"(a[1]), "r"(a[2]), "r"(a[3]), "r"(b[0]), "r"(b[1]));
}

// ---------------- CSR build ---------------------------------------------------
__global__ void k_zero_rowptr() {
    int i = blockIdx.x * blockDim.x + threadIdx.x;
    if (i <= N_NODES) g_rowptr[i] = 0;
}
__global__ void k_hist(const int* __restrict__ dst) {
    int e = blockIdx.x * blockDim.x + threadIdx.x;
    if (e < N_EDGES) atomicAdd(&g_rowptr[dst[e] + 1], 1);
}
__global__ void __launch_bounds__(1024) k_scan() {
    __shared__ int s_w[32];
    __shared__ int s_carry;
    int tid = threadIdx.x, lane = tid & 31, wid = tid >> 5;
    if (tid == 0) s_carry = 0;
    __syncthreads();
    const int n = N_NODES + 1;
    for (int base = 0; base < n; base += 1024) {
        int i = base + tid;
        int v = (i < n) ? g_rowptr[i] : 0;
        #pragma unroll
        for (int off = 1; off < 32; off <<= 1) {
            int t = __shfl_up_sync(0xffffffffu, v, off);
            if (lane >= off) v += t;
        }
        if (lane == 31) s_w[wid] = v;
        __syncthreads();
        if (wid == 0) {
            int s = s_w[lane];
            #pragma unroll
            for (int off = 1; off < 32; off <<= 1) {
                int t = __shfl_up_sync(0xffffffffu, s, off);
                if (lane >= off) s += t;
            }
            s_w[lane] = s;
        }
        __syncthreads();
        int res = v + (wid > 0 ? s_w[wid - 1] : 0) + s_carry;
        if (i < n) g_rowptr[i] = res;
        if (i < N_NODES) g_cursor[i] = res;
        __syncthreads();
        if (tid == 1023) s_carry = res;
        __syncthreads();
    }
}
__global__ void k_scatter(const int* __restrict__ src, const int* __restrict__ dst,
                          const int* __restrict__ et) {
    int e = blockIdx.x * blockDim.x + threadIdx.x;
    if (e < N_EDGES) {
        int slot = atomicAdd(&g_cursor[dst[e]], 1);
        g_epack[slot] = src[e] | (et[e] << 20);
    }
}

// ---------------- rel projection, both layers ---------------------------------
__global__ void k_relproj(const float* __restrict__ rel_emb,
                          const float* __restrict__ We,
                          const float* __restrict__ be) {
    int r = blockIdx.x % RNUM, l = blockIdx.x / RNUM;
    int o = threadIdx.x;
    const float* W = We + l * FDIM * FDIM;
    float acc = be[l * FDIM + o];
    #pragma unroll 4
    for (int f = 0; f < FDIM; f++)
        acc += rel_emb[r * FDIM + f] * W[f * FDIM + o];
    g_rel[(l * RNUM + r) * FDIM + o] = acc;
}

// ---------------- prep: convert 6 weight matrices to fp16 ---------------------
__global__ void k_prepw(const float* __restrict__ Wq, const float* __restrict__ Wk,
                        const float* __restrict__ Wv) {
    int i = blockIdx.x * 256 + threadIdx.x;      // 6*16384 elements
    int mat = i >> 14, r = i & 16383;
    int sel = mat % 3, layer = mat / 3;
    const float* W = (sel == 0 ? Wq : sel == 1 ? Wk : Wv) + layer * FDIM * FDIM;
    g_wh[i] = __float2half_rn(W[r]);
}

// ---------------- fused QKV GEMM via HMMA (m16n8k16, fp16 in, fp32 acc) -------
__global__ void __launch_bounds__(256) k_gemm_qkv(const float* __restrict__ Aext, int layer,
                                                  const float* __restrict__ bq,
                                                  const float* __restrict__ bk,
                                                  const float* __restrict__ bv) {
    const float* A = layer ? g_h : Aext;
    extern __shared__ __half sm[];
    __half (*As)[136] = (__half(*)[136])sm;               // [128][136]
    __half (*Bs)[136] = (__half(*)[136])(sm + 128 * 136); // [128][136], [k][n]

    int tid = threadIdx.x, wid = tid >> 5, lane = tid & 31;
    int wm = wid & 3, wn = wid >> 2;
    int rowBase = blockIdx.x * 128;
    unsigned sA = smem_u32(As), sB = smem_u32(Bs);

    #pragma unroll
    for (int t = 0; t < 16; t++) {
        int v = tid + t * 256;
        int r = v >> 5, c4 = v & 31;
        int grow = rowBase + r;
        float4 a = (grow < N_NODES)
            ? *(const float4*)(A + (size_t)grow * FDIM + c4 * 4)
            : make_float4(0.f, 0.f, 0.f, 0.f);
        *(__half2*)&As[r][c4 * 4]     = __floats2half2_rn(a.x, a.y);
        *(__half2*)&As[r][c4 * 4 + 2] = __floats2half2_rn(a.z, a.w);
    }

    unsigned quad = lane >> 3, lr = lane & 7;
    int g = lane >> 2, tg = lane & 3;

    #pragma unroll 1
    for (int sel = 0; sel < 3; sel++) {
        __syncthreads();
        {
            const __half* Wsrc = g_wh + (size_t)(layer * 3 + sel) * 16384;
            #pragma unroll
            for (int t = 0; t < 8; t++) {
                int v = tid + t * 256;
                int r = v >> 4, c8 = v & 15;
                *(uint4*)&Bs[r][c8 * 8] = *(const uint4*)(Wsrc + r * FDIM + c8 * 8);
            }
        }
        __syncthreads();

        float acc[2][8][4];
        #pragma unroll
        for (int i = 0; i < 2; i++)
            #pragma unroll
            for (int j = 0; j < 8; j++)
                #pragma unroll
                for (int c = 0; c < 4; c++) acc[i][j][c] = 0.f;

        #pragma unroll
        for (int ks = 0; ks < 8; ks++) {
            int k0 = ks * 16;
            unsigned af[2][4], bf[4][4];
            #pragma unroll
            for (int i = 0; i < 2; i++) {
                int arow = wm * 32 + i * 16 + ((quad & 1) << 3) + lr;
                int acol = k0 + ((quad >> 1) << 3);
                ldsm4(af[i], sA + (arow * 136 + acol) * 2);
            }
            #pragma unroll
            for (int j2 = 0; j2 < 4; j2++) {
                int brow = k0 + ((quad & 1) << 3) + lr;
                int bcol = wn * 64 + j2 * 16 + ((quad >> 1) << 3);
                ldsm4t(bf[j2], sB + (brow * 136 + bcol) * 2);
            }
            #pragma unroll
            for (int i = 0; i < 2; i++)
                #pragma unroll
                for (int j = 0; j < 8; j++)
                    mma16816(acc[i][j], af[i], &bf[j >> 1][(j & 1) * 2]);
        }

        const float* bias = (sel == 0 ? bq : sel == 1 ? bk : bv) + layer * FDIM;
        #pragma unroll
        for (int i = 0; i < 2; i++) {
            int r0 = rowBase + wm * 32 + i * 16 + g;
            int r1 = r0 + 8;
            #pragma unroll
            for (int j = 0; j < 8; j++) {
                int col = wn * 64 + j * 8 + tg * 2;
                float2 b2 = *(const float2*)(bias + col);
                float d0 = acc[i][j][0] + b2.x, d1 = acc[i][j][1] + b2.y;
                float d2 = acc[i][j][2] + b2.x, d3 = acc[i][j][3] + b2.y;
                if (sel == 0) {
                    if (r0 < N_NODES) *(float2*)(g_q + (size_t)r0 * FDIM + col) = make_float2(d0, d1);
                    if (r1 < N_NODES) *(float2*)(g_q + (size_t)r1 * FDIM + col) = make_float2(d2, d3);
                } else {
                    int off = (sel == 1) ? 0 : FDIM;
                    if (r0 < N_NODES)
                        *(__half2*)(g_kvh + (size_t)r0 * 2 * FDIM + off + col) = __floats2half2_rn(d0, d1);
                    if (r1 < N_NODES)
                        *(__half2*)(g_kvh + (size_t)r1 * 2 * FDIM + off + col) = __floats2half2_rn(d2, d3);
                }
            }
        }
    }
}

// ---------------- fused attention: warp per dst node, 8 lanes per head --------
// No online max: scores are bounded (|score| << 30 by construction), softmax is
// shift-invariant, so exp2 around 0 is exact. Only cross-edge chain is the FMA
// accumulate. SCALE2F folded into q registers.
template <int LAYER>
__global__ void __launch_bounds__(256) k_attn(const float* __restrict__ inputs,
                                              const float* __restrict__ Wout,
                                              const float* __restrict__ bout,
                                              const float* __restrict__ cent,
                                              const float* __restrict__ gamma,
                                              const float* __restrict__ beta,
                                              float* __restrict__ out) {
    __shared__ float4 s_rel[RNUM * 32];
    {
        const float4* rel4 = (const float4*)(g_rel + LAYER * RNUM * FDIM);
        for (int i = threadIdx.x; i < RNUM * 32; i += 256) s_rel[i] = rel4[i];
    }
    __syncthreads();

    int gw = (blockIdx.x * 256 + threadIdx.x) >> 5;
    int lane = threadIdx.x & 31;
    if (gw >= N_NODES) return;

    const float* hin = LAYER ? g_h : inputs;
    const uint2* kvp = (const uint2*)g_kvh;     // 4 halves per uint2; 64 per node
    int idx = gw * 32 + lane;

    float4 qr = ((const float4*)g_q)[idx];
    qr.x *= SCALE2F; qr.y *= SCALE2F; qr.z *= SCALE2F; qr.w *= SCALE2F;
    float ss = 0.f;
    float4 acc = make_float4(0.f, 0.f, 0.f, 0.f);

    int e0 = g_rowptr[gw], e1 = g_rowptr[gw + 1];
    uint2 pk, pv;
    float4 pr4;
    if (e0 < e1) {
        int p = g_epack[e0];
        int si = (p & 0xFFFFF) * 64 + lane;
        pk = kvp[si];
        pv = kvp[si + 32];
        pr4 = s_rel[(p >> 20) * 32 + lane];
    }
    for (int e = e0; e < e1; e++) {
        uint2 kr = pk, vr = pv;
        float4 rel = pr4;
        if (e + 1 < e1) {
            int p = g_epack[e + 1];
            int si = (p & 0xFFFFF) * 64 + lane;
            pk = kvp[si];
            pv = kvp[si + 32];
            pr4 = s_rel[(p >> 20) * 32 + lane];
        }
        float2 k01 = __half22float2(*(__half2*)&kr.x);
        float2 k23 = __half22float2(*(__half2*)&kr.y);
        float pr = qr.x * (k01.x + rel.x) + qr.y * (k01.y + rel.y)
                 + qr.z * (k23.x + rel.z) + qr.w * (k23.y + rel.w);
        pr += __shfl_xor_sync(0xffffffffu, pr, 4);
        pr += __shfl_xor_sync(0xffffffffu, pr, 2);
        pr += __shfl_xor_sync(0xffffffffu, pr, 1);
        float w = exp2f(pr);
        float2 v01 = __half22float2(*(__half2*)&vr.x);
        float2 v23 = __half22float2(*(__half2*)&vr.y);
        ss += w;
        acc.x += w * (v01.x + rel.x);
        acc.y += w * (v01.y + rel.y);
        acc.z += w * (v23.x + rel.z);
        acc.w += w * (v23.y + rel.w);
    }

    float inv = 1.f / (ss + 1e-9f);
    float4 hi = ((const float4*)hin)[idx];
    float4 x;
    x.x = acc.x * inv + hi.x;
    x.y = acc.y * inv + hi.y;
    x.z = acc.z * inv + hi.z;
    x.w = acc.w * inv + hi.w;
    x.x = (x.x > 0.f) ? x.x : (__expf(x.x) - 1.f);
    x.y = (x.y > 0.f) ? x.y : (__expf(x.y) - 1.f);
    x.z = (x.z > 0.f) ? x.z : (__expf(x.z) - 1.f);
    x.w = (x.w > 0.f) ? x.w : (__expf(x.w) - 1.f);

    if (LAYER == 0) {
        ((float4*)g_h)[idx] = x;
    } else {
        float4 w4 = ((const float4*)Wout)[lane];
        float p = x.x * w4.x + x.y * w4.y + x.z * w4.z + x.w * w4.w;
        p += __shfl_xor_sync(0xffffffffu, p, 16);
        p += __shfl_xor_sync(0xffffffffu, p, 8);
        p += __shfl_xor_sync(0xffffffffu, p, 4);
        p += __shfl_xor_sync(0xffffffffu, p, 2);
        p += __shfl_xor_sync(0xffffffffu, p, 1);
        if (lane == 0) {
            float lg = p + bout[0];
            float sc = cent[gw] * gamma[0] + beta[0];
            float r = sc * lg;
            out[gw] = (r > 0.f) ? r : 0.f;
        }
    }
}

// ---------------- launch ------------------------------------------------------
extern "C" void kernel_launch(void* const* d_in, const int* in_sizes, int n_in,
                              void* d_out, int out_size) {
    const float* inputs  = (const float*)d_in[0];
    const int*   et      = (const int*)d_in[1];
    const int*   src     = (const int*)d_in[2];
    const int*   dst     = (const int*)d_in[3];
    const float* cent    = (const float*)d_in[4];
    const float* rel_emb = (const float*)d_in[5];
    const float* Wq      = (const float*)d_in[6];
    const float* bq      = (const float*)d_in[7];
    const float* Wk      = (const float*)d_in[8];
    const float* bk      = (const float*)d_in[9];
    const float* Wv      = (const float*)d_in[10];
    const float* bv      = (const float*)d_in[11];
    const float* We      = (const float*)d_in[12];
    const float* be      = (const float*)d_in[13];
    const float* Wout    = (const float*)d_in[14];
    const float* bout    = (const float*)d_in[15];
    const float* gamma   = (const float*)d_in[16];
    const float* beta    = (const float*)d_in[17];
    float* out = (float*)d_out;

    const int GEMM_SMEM = 2 * 128 * 136 * 2;   // 69632 bytes

    static cudaStream_t s1 = nullptr, s2 = nullptr;
    static cudaEvent_t ev_fork = nullptr, ev_prep = nullptr, ev_rel = nullptr, ev_csr = nullptr;
    if (s1 == nullptr) {
        cudaStreamCreateWithFlags(&s1, cudaStreamNonBlocking);
        cudaStreamCreateWithFlags(&s2, cudaStreamNonBlocking);
        cudaEventCreateWithFlags(&ev_fork, cudaEventDisableTiming);
        cudaEventCreateWithFlags(&ev_prep, cudaEventDisableTiming);
        cudaEventCreateWithFlags(&ev_rel, cudaEventDisableTiming);
        cudaEventCreateWithFlags(&ev_csr, cudaEventDisableTiming);
        cudaFuncSetAttribute(k_gemm_qkv, cudaFuncAttributeMaxDynamicSharedMemorySize, GEMM_SMEM);
    }

    cudaEventRecord(ev_fork, 0);

    // s1: W fp16 conversion, then rel projections
    cudaStreamWaitEvent(s1, ev_fork, 0);
    k_prepw<<<(6 * FDIM * FDIM) / 256, 256, 0, s1>>>(Wq, Wk, Wv);
    cudaEventRecord(ev_prep, s1);
    k_relproj<<<NLAYER * RNUM, FDIM, 0, s1>>>(rel_emb, We, be);
    cudaEventRecord(ev_rel, s1);

    // s2: CSR build
    cudaStreamWaitEvent(s2, ev_fork, 0);
    k_zero_rowptr<<<(N_NODES + 256) / 256, 256, 0, s2>>>();
    k_hist<<<(N_EDGES + 255) / 256, 256, 0, s2>>>(dst);
    k_scan<<<1, 1024, 0, s2>>>();
    k_scatter<<<(N_EDGES + 255) / 256, 256, 0, s2>>>(src, dst, et);
    cudaEventRecord(ev_csr, s2);

    int attn_blocks = (N_NODES * 32 + 255) / 256;

    // layer 0
    cudaStreamWaitEvent(0, ev_prep, 0);
    k_gemm_qkv<<<NTILES, 256, GEMM_SMEM>>>(inputs, 0, bq, bk, bv);
    cudaStreamWaitEvent(0, ev_csr, 0);
    cudaStreamWaitEvent(0, ev_rel, 0);
    k_attn<0><<<attn_blocks, 256>>>(inputs, Wout, bout, cent, gamma, beta, out);

    // layer 1 (+ fused output head)
    k_gemm_qkv<<<NTILES, 256, GEMM_SMEM>>>(inputs, 1, bq, bk, bv);
    k_attn<1><<<attn_blocks, 256>>>(inputs, Wout, bout, cent, gamma, beta, out);
}

// round 13
// speedup vs baseline: 1.4822x; 1.4822x over previous
#include <cuda_runtime.h>
#include <cuda_fp16.h>
#include <cstdint>
#include <math.h>

#define N_NODES 50000
#define N_EDGES 800000
#define FDIM    128
#define RNUM    11
#define NLAYER  2
#define NTILES  391                              // ceil(50000/128)
#define SCALE2F (0.17677669529663687f * 1.4426950408889634f)   // (1/sqrt32)*log2(e)

typedef unsigned long long ull;

// ---------------- scratch (device globals; no allocation allowed) -------------
__device__ float  g_h[N_NODES * FDIM];
__device__ float  g_q[N_NODES * FDIM];
__device__ __align__(16) __half g_kvh[N_NODES * 2 * FDIM]; // per node: 128 k, 128 v
__device__ __align__(16) __half g_wh[6 * FDIM * FDIM];     // fp16 W, [layer*3+sel][k][n]
__device__ float  g_rel[NLAYER * RNUM * FDIM];
__device__ int    g_rowptr[N_NODES + 1];
__device__ int    g_cursor[N_NODES];
__device__ int    g_epack[N_EDGES];              // src | (edge_type << 20)

// ---------------- PTX helpers --------------------------------------------------
__device__ __forceinline__ unsigned smem_u32(const void* p) {
    unsigned a;
    asm("{ .reg .u64 t; cvta.to.shared.u64 t, %1; cvt.u32.u64 %0, t; }" : "=r"(a) : "l"(p));
    return a;
}
__device__ __forceinline__ void ldsm4(unsigned* r, unsigned addr) {
    asm volatile("ldmatrix.sync.aligned.m8n8.x4.shared.b16 {%0,%1,%2,%3}, [%4];"
                 : "=r"(r[0]), "=r"(r[1]), "=r"(r[2]), "=r"(r[3]) : "r"(addr));
}
__device__ __forceinline__ void ldsm4t(unsigned* r, unsigned addr) {
    asm volatile("ldmatrix.sync.aligned.m8n8.x4.trans.shared.b16 {%0,%1,%2,%3}, [%4];"
                 : "=r"(r[0]), "=r"(r[1]), "=r"(r[2]), "=r"(r[3]) : "r"(addr));
}
__device__ __forceinline__ void mma16816(float* d, const unsigned* a, const unsigned* b) {
    asm volatile(
        "mma.sync.aligned.m16n8k16.row.col.f32.f16.f16.f32 "
        "{%0,%1,%2,%3}, {%4,%5,%6,%7}, {%8,%9}, {%0,%1,%2,%3};"
        : "+f"(d[0]), "+f"(d[1]), "+f"(d[2]), "+f"(d[3])
        : "r"(a[0]), "r"(a[1]), "r"(a[2]), "r"(a[3]), "r"(b[0]), "r"(b[1]));
}

// ---------------- CSR build ---------------------------------------------------
__global__ void k_zero_rowptr() {
    int i = blockIdx.x * blockDim.x + threadIdx.x;
    if (i <= N_NODES) g_rowptr[i] = 0;
}
__global__ void k_hist(const int* __restrict__ dst) {
    int e = blockIdx.x * blockDim.x + threadIdx.x;
    if (e < N_EDGES) atomicAdd(&g_rowptr[dst[e] + 1], 1);
}
__global__ void __launch_bounds__(1024) k_scan() {
    __shared__ int s_w[32];
    __shared__ int s_carry;
    int tid = threadIdx.x, lane = tid & 31, wid = tid >> 5;
    if (tid == 0) s_carry = 0;
    __syncthreads();
    const int n = N_NODES + 1;
    for (int base = 0; base < n; base += 1024) {
        int i = base + tid;
        int v = (i < n) ? g_rowptr[i] : 0;
        #pragma unroll
        for (int off = 1; off < 32; off <<= 1) {
            int t = __shfl_up_sync(0xffffffffu, v, off);
            if (lane >= off) v += t;
        }
        if (lane == 31) s_w[wid] = v;
        __syncthreads();
        if (wid == 0) {
            int s = s_w[lane];
            #pragma unroll
            for (int off = 1; off < 32; off <<= 1) {
                int t = __shfl_up_sync(0xffffffffu, s, off);
                if (lane >= off) s += t;
            }
            s_w[lane] = s;
        }
        __syncthreads();
        int res = v + (wid > 0 ? s_w[wid - 1] : 0) + s_carry;
        if (i < n) g_rowptr[i] = res;
        if (i < N_NODES) g_cursor[i] = res;
        __syncthreads();
        if (tid == 1023) s_carry = res;
        __syncthreads();
    }
}
__global__ void k_scatter(const int* __restrict__ src, const int* __restrict__ dst,
                          const int* __restrict__ et) {
    int e = blockIdx.x * blockDim.x + threadIdx.x;
    if (e < N_EDGES) {
        int slot = atomicAdd(&g_cursor[dst[e]], 1);
        g_epack[slot] = src[e] | (et[e] << 20);
    }
}

// ---------------- rel projection, both layers ---------------------------------
__global__ void k_relproj(const float* __restrict__ rel_emb,
                          const float* __restrict__ We,
                          const float* __restrict__ be) {
    int r = blockIdx.x % RNUM, l = blockIdx.x / RNUM;
    int o = threadIdx.x;
    const float* W = We + l * FDIM * FDIM;
    float acc = be[l * FDIM + o];
    #pragma unroll 4
    for (int f = 0; f < FDIM; f++)
        acc += rel_emb[r * FDIM + f] * W[f * FDIM + o];
    g_rel[(l * RNUM + r) * FDIM + o] = acc;
}

// ---------------- prep: convert 6 weight matrices to fp16 ---------------------
__global__ void k_prepw(const float* __restrict__ Wq, const float* __restrict__ Wk,
                        const float* __restrict__ Wv) {
    int i = blockIdx.x * 256 + threadIdx.x;      // 6*16384 elements
    int mat = i >> 14, r = i & 16383;
    int sel = mat % 3, layer = mat / 3;
    const float* W = (sel == 0 ? Wq : sel == 1 ? Wk : Wv) + layer * FDIM * FDIM;
    g_wh[i] = __float2half_rn(W[r]);
}

// ---------------- fused QKV GEMM via HMMA (m16n8k16, fp16 in, fp32 acc) -------
__global__ void __launch_bounds__(256) k_gemm_qkv(const float* __restrict__ Aext, int layer,
                                                  const float* __restrict__ bq,
                                                  const float* __restrict__ bk,
                                                  const float* __restrict__ bv) {
    const float* A = layer ? g_h : Aext;
    extern __shared__ __half sm[];
    __half (*As)[136] = (__half(*)[136])sm;               // [128][136]
    __half (*Bs)[136] = (__half(*)[136])(sm + 128 * 136); // [128][136], [k][n]

    int tid = threadIdx.x, wid = tid >> 5, lane = tid & 31;
    int wm = wid & 3, wn = wid >> 2;
    int rowBase = blockIdx.x * 128;
    unsigned sA = smem_u32(As), sB = smem_u32(Bs);

    #pragma unroll
    for (int t = 0; t < 16; t++) {
        int v = tid + t * 256;
        int r = v >> 5, c4 = v & 31;
        int grow = rowBase + r;
        float4 a = (grow < N_NODES)
            ? *(const float4*)(A + (size_t)grow * FDIM + c4 * 4)
            : make_float4(0.f, 0.f, 0.f, 0.f);
        *(__half2*)&As[r][c4 * 4]     = __floats2half2_rn(a.x, a.y);
        *(__half2*)&As[r][c4 * 4 + 2] = __floats2half2_rn(a.z, a.w);
    }

    unsigned quad = lane >> 3, lr = lane & 7;
    int g = lane >> 2, tg = lane & 3;

    #pragma unroll 1
    for (int sel = 0; sel < 3; sel++) {
        __syncthreads();
        {
            const __half* Wsrc = g_wh + (size_t)(layer * 3 + sel) * 16384;
            #pragma unroll
            for (int t = 0; t < 8; t++) {
                int v = tid + t * 256;
                int r = v >> 4, c8 = v & 15;
                *(uint4*)&Bs[r][c8 * 8] = *(const uint4*)(Wsrc + r * FDIM + c8 * 8);
            }
        }
        __syncthreads();

        float acc[2][8][4];
        #pragma unroll
        for (int i = 0; i < 2; i++)
            #pragma unroll
            for (int j = 0; j < 8; j++)
                #pragma unroll
                for (int c = 0; c < 4; c++) acc[i][j][c] = 0.f;

        #pragma unroll
        for (int ks = 0; ks < 8; ks++) {
            int k0 = ks * 16;
            unsigned af[2][4], bf[4][4];
            #pragma unroll
            for (int i = 0; i < 2; i++) {
                int arow = wm * 32 + i * 16 + ((quad & 1) << 3) + lr;
                int acol = k0 + ((quad >> 1) << 3);
                ldsm4(af[i], sA + (arow * 136 + acol) * 2);
            }
            #pragma unroll
            for (int j2 = 0; j2 < 4; j2++) {
                int brow = k0 + ((quad & 1) << 3) + lr;
                int bcol = wn * 64 + j2 * 16 + ((quad >> 1) << 3);
                ldsm4t(bf[j2], sB + (brow * 136 + bcol) * 2);
            }
            #pragma unroll
            for (int i = 0; i < 2; i++)
                #pragma unroll
                for (int j = 0; j < 8; j++)
                    mma16816(acc[i][j], af[i], &bf[j >> 1][(j & 1) * 2]);
        }

        const float* bias = (sel == 0 ? bq : sel == 1 ? bk : bv) + layer * FDIM;
        #pragma unroll
        for (int i = 0; i < 2; i++) {
            int r0 = rowBase + wm * 32 + i * 16 + g;
            int r1 = r0 + 8;
            #pragma unroll
            for (int j = 0; j < 8; j++) {
                int col = wn * 64 + j * 8 + tg * 2;
                float2 b2 = *(const float2*)(bias + col);
                float d0 = acc[i][j][0] + b2.x, d1 = acc[i][j][1] + b2.y;
                float d2 = acc[i][j][2] + b2.x, d3 = acc[i][j][3] + b2.y;
                if (sel == 0) {
                    if (r0 < N_NODES) *(float2*)(g_q + (size_t)r0 * FDIM + col) = make_float2(d0, d1);
                    if (r1 < N_NODES) *(float2*)(g_q + (size_t)r1 * FDIM + col) = make_float2(d2, d3);
                } else {
                    int off = (sel == 1) ? 0 : FDIM;
                    if (r0 < N_NODES)
                        *(__half2*)(g_kvh + (size_t)r0 * 2 * FDIM + off + col) = __floats2half2_rn(d0, d1);
                    if (r1 < N_NODES)
                        *(__half2*)(g_kvh + (size_t)r1 * 2 * FDIM + off + col) = __floats2half2_rn(d2, d3);
                }
            }
        }
    }
}

// ---------------- fused attention: warp per dst node, 8 lanes per head --------
// No online max: scores are bounded (|score| << 30 by construction), softmax is
// shift-invariant, so exp2 around 0 is exact. Only cross-edge chain is the FMA
// accumulate. SCALE2F folded into q registers.
template <int LAYER>
__global__ void __launch_bounds__(256) k_attn(const float* __restrict__ inputs,
                                              const float* __restrict__ Wout,
                                              const float* __restrict__ bout,
                                              const float* __restrict__ cent,
                                              const float* __restrict__ gamma,
                                              const float* __restrict__ beta,
                                              float* __restrict__ out) {
    __shared__ float4 s_rel[RNUM * 32];
    {
        const float4* rel4 = (const float4*)(g_rel + LAYER * RNUM * FDIM);
        for (int i = threadIdx.x; i < RNUM * 32; i += 256) s_rel[i] = rel4[i];
    }
    __syncthreads();

    int gw = (blockIdx.x * 256 + threadIdx.x) >> 5;
    int lane = threadIdx.x & 31;
    if (gw >= N_NODES) return;

    const float* hin = LAYER ? g_h : inputs;
    const uint2* kvp = (const uint2*)g_kvh;     // 4 halves per uint2; 64 per node
    int idx = gw * 32 + lane;

    float4 qr = ((const float4*)g_q)[idx];
    qr.x *= SCALE2F; qr.y *= SCALE2F; qr.z *= SCALE2F; qr.w *= SCALE2F;
    float ss = 0.f;
    float4 acc = make_float4(0.f, 0.f, 0.f, 0.f);

    int e0 = g_rowptr[gw], e1 = g_rowptr[gw + 1];
    uint2 pk, pv;
    float4 pr4;
    if (e0 < e1) {
        int p = g_epack[e0];
        int si = (p & 0xFFFFF) * 64 + lane;
        pk = kvp[si];
        pv = kvp[si + 32];
        pr4 = s_rel[(p >> 20) * 32 + lane];
    }
    for (int e = e0; e < e1; e++) {
        uint2 kr = pk, vr = pv;
        float4 rel = pr4;
        if (e + 1 < e1) {
            int p = g_epack[e + 1];
            int si = (p & 0xFFFFF) * 64 + lane;
            pk = kvp[si];
            pv = kvp[si + 32];
            pr4 = s_rel[(p >> 20) * 32 + lane];
        }
        float2 k01 = __half22float2(*(__half2*)&kr.x);
        float2 k23 = __half22float2(*(__half2*)&kr.y);
        float pr = qr.x * (k01.x + rel.x) + qr.y * (k01.y + rel.y)
                 + qr.z * (k23.x + rel.z) + qr.w * (k23.y + rel.w);
        pr += __shfl_xor_sync(0xffffffffu, pr, 4);
        pr += __shfl_xor_sync(0xffffffffu, pr, 2);
        pr += __shfl_xor_sync(0xffffffffu, pr, 1);
        float w = exp2f(pr);
        float2 v01 = __half22float2(*(__half2*)&vr.x);
        float2 v23 = __half22float2(*(__half2*)&vr.y);
        ss += w;
        acc.x += w * (v01.x + rel.x);
        acc.y += w * (v01.y + rel.y);
        acc.z += w * (v23.x + rel.z);
        acc.w += w * (v23.y + rel.w);
    }

    float inv = 1.f / (ss + 1e-9f);
    float4 hi = ((const float4*)hin)[idx];
    float4 x;
    x.x = acc.x * inv + hi.x;
    x.y = acc.y * inv + hi.y;
    x.z = acc.z * inv + hi.z;
    x.w = acc.w * inv + hi.w;
    x.x = (x.x > 0.f) ? x.x : (__expf(x.x) - 1.f);
    x.y = (x.y > 0.f) ? x.y : (__expf(x.y) - 1.f);
    x.z = (x.z > 0.f) ? x.z : (__expf(x.z) - 1.f);
    x.w = (x.w > 0.f) ? x.w : (__expf(x.w) - 1.f);

    if (LAYER == 0) {
        ((float4*)g_h)[idx] = x;
    } else {
        float4 w4 = ((const float4*)Wout)[lane];
        float p = x.x * w4.x + x.y * w4.y + x.z * w4.z + x.w * w4.w;
        p += __shfl_xor_sync(0xffffffffu, p, 16);
        p += __shfl_xor_sync(0xffffffffu, p, 8);
        p += __shfl_xor_sync(0xffffffffu, p, 4);
        p += __shfl_xor_sync(0xffffffffu, p, 2);
        p += __shfl_xor_sync(0xffffffffu, p, 1);
        if (lane == 0) {
            float lg = p + bout[0];
            float sc = cent[gw] * gamma[0] + beta[0];
            float r = sc * lg;
            out[gw] = (r > 0.f) ? r : 0.f;
        }
    }
}

// ---------------- launch ------------------------------------------------------
extern "C" void kernel_launch(void* const* d_in, const int* in_sizes, int n_in,
                              void* d_out, int out_size) {
    const float* inputs  = (const float*)d_in[0];
    const int*   et      = (const int*)d_in[1];
    const int*   src     = (const int*)d_in[2];
    const int*   dst     = (const int*)d_in[3];
    const float* cent    = (const float*)d_in[4];
    const float* rel_emb = (const float*)d_in[5];
    const float* Wq      = (const float*)d_in[6];
    const float* bq      = (const float*)d_in[7];
    const float* Wk      = (const float*)d_in[8];
    const float* bk      = (const float*)d_in[9];
    const float* Wv      = (const float*)d_in[10];
    const float* bv      = (const float*)d_in[11];
    const float* We      = (const float*)d_in[12];
    const float* be      = (const float*)d_in[13];
    const float* Wout    = (const float*)d_in[14];
    const float* bout    = (const float*)d_in[15];
    const float* gamma   = (const float*)d_in[16];
    const float* beta    = (const float*)d_in[17];
    float* out = (float*)d_out;

    const int GEMM_SMEM = 2 * 128 * 136 * 2;   // 69632 bytes

    static cudaStream_t s1 = nullptr, s2 = nullptr;
    static cudaEvent_t ev_fork = nullptr, ev_prep = nullptr, ev_rel = nullptr, ev_csr = nullptr;
    if (s1 == nullptr) {
        cudaStreamCreateWithFlags(&s1, cudaStreamNonBlocking);
        cudaStreamCreateWithFlags(&s2, cudaStreamNonBlocking);
        cudaEventCreateWithFlags(&ev_fork, cudaEventDisableTiming);
        cudaEventCreateWithFlags(&ev_prep, cudaEventDisableTiming);
        cudaEventCreateWithFlags(&ev_rel, cudaEventDisableTiming);
        cudaEventCreateWithFlags(&ev_csr, cudaEventDisableTiming);
        cudaFuncSetAttribute(k_gemm_qkv, cudaFuncAttributeMaxDynamicSharedMemorySize, GEMM_SMEM);
    }

    cudaEventRecord(ev_fork, 0);

    // s1: W fp16 conversion, then rel projections
    cudaStreamWaitEvent(s1, ev_fork, 0);
    k_prepw<<<(6 * FDIM * FDIM) / 256, 256, 0, s1>>>(Wq, Wk, Wv);
    cudaEventRecord(ev_prep, s1);
    k_relproj<<<NLAYER * RNUM, FDIM, 0, s1>>>(rel_emb, We, be);
    cudaEventRecord(ev_rel, s1);

    // s2: CSR build
    cudaStreamWaitEvent(s2, ev_fork, 0);
    k_zero_rowptr<<<(N_NODES + 256) / 256, 256, 0, s2>>>();
    k_hist<<<(N_EDGES + 255) / 256, 256, 0, s2>>>(dst);
    k_scan<<<1, 1024, 0, s2>>>();
    k_scatter<<<(N_EDGES + 255) / 256, 256, 0, s2>>>(src, dst, et);
    cudaEventRecord(ev_csr, s2);

    int attn_blocks = (N_NODES * 32 + 255) / 256;

    // layer 0
    cudaStreamWaitEvent(0, ev_prep, 0);
    k_gemm_qkv<<<NTILES, 256, GEMM_SMEM>>>(inputs, 0, bq, bk, bv);
    cudaStreamWaitEvent(0, ev_csr, 0);
    cudaStreamWaitEvent(0, ev_rel, 0);
    k_attn<0><<<attn_blocks, 256>>>(inputs, Wout, bout, cent, gamma, beta, out);

    // layer 1 (+ fused output head)
    k_gemm_qkv<<<NTILES, 256, GEMM_SMEM>>>(inputs, 1, bq, bk, bv);
    k_attn<1><<<attn_blocks, 256>>>(inputs, Wout, bout, cent, gamma, beta, out);
}

// round 14
// speedup vs baseline: 1.4841x; 1.0012x over previous
#include <cuda_runtime.h>
#include <cuda_fp16.h>
#include <cstdint>
#include <math.h>

#define N_NODES 50000
#define N_EDGES 800000
#define FDIM    128
#define RNUM    11
#define NLAYER  2
#define NTILES  391                              // ceil(50000/128)
#define SCALE2F (0.17677669529663687f * 1.4426950408889634f)   // (1/sqrt32)*log2(e)

typedef unsigned long long ull;

// ---------------- scratch (device globals; no allocation allowed) -------------
__device__ float  g_h[N_NODES * FDIM];
__device__ float  g_q[N_NODES * FDIM];
__device__ __align__(16) __half g_kvh[N_NODES * 2 * FDIM]; // per node: 128 k, 128 v
__device__ __align__(16) __half g_wh[6 * FDIM * FDIM];     // fp16 W, [layer*3+sel][k][n]
__device__ float  g_rel[NLAYER * RNUM * FDIM];
__device__ int    g_rowptr[N_NODES + 1];
__device__ int    g_cursor[N_NODES];
__device__ int    g_epack[N_EDGES];              // src | (edge_type << 20)

// ---------------- PTX helpers --------------------------------------------------
__device__ __forceinline__ unsigned smem_u32(const void* p) {
    unsigned a;
    asm("{ .reg .u64 t; cvta.to.shared.u64 t, %1; cvt.u32.u64 %0, t; }" : "=r"(a) : "l"(p));
    return a;
}
__device__ __forceinline__ void ldsm4(unsigned* r, unsigned addr) {
    asm volatile("ldmatrix.sync.aligned.m8n8.x4.shared.b16 {%0,%1,%2,%3}, [%4];"
                 : "=r"(r[0]), "=r"(r[1]), "=r"(r[2]), "=r"(r[3]) : "r"(addr));
}
__device__ __forceinline__ void ldsm4t(unsigned* r, unsigned addr) {
    asm volatile("ldmatrix.sync.aligned.m8n8.x4.trans.shared.b16 {%0,%1,%2,%3}, [%4];"
                 : "=r"(r[0]), "=r"(r[1]), "=r"(r[2]), "=r"(r[3]) : "r"(addr));
}
__device__ __forceinline__ void mma16816(float* d, const unsigned* a, const unsigned* b) {
    asm volatile(
        "mma.sync.aligned.m16n8k16.row.col.f32.f16.f16.f32 "
        "{%0,%1,%2,%3}, {%4,%5,%6,%7}, {%8,%9}, {%0,%1,%2,%3};"
        : "+f"(d[0]), "+f"(d[1]), "+f"(d[2]), "+f"(d[3])
        : "r"(a[0]), "r"(a[1]), "r"(a[2]), "r"(a[3]), "r"(b[0]), "r"(b[1]));
}

// ---------------- CSR build ---------------------------------------------------
__global__ void k_zero_rowptr() {
    int i = blockIdx.x * blockDim.x + threadIdx.x;
    if (i <= N_NODES) g_rowptr[i] = 0;
}
__global__ void k_hist(const int* __restrict__ dst) {
    int e = blockIdx.x * blockDim.x + threadIdx.x;
    if (e < N_EDGES) atomicAdd(&g_rowptr[dst[e] + 1], 1);
}
__global__ void __launch_bounds__(1024) k_scan() {
    __shared__ int s_w[32];
    __shared__ int s_carry;
    int tid = threadIdx.x, lane = tid & 31, wid = tid >> 5;
    if (tid == 0) s_carry = 0;
    __syncthreads();
    const int n = N_NODES + 1;
    for (int base = 0; base < n; base += 1024) {
        int i = base + tid;
        int v = (i < n) ? g_rowptr[i] : 0;
        #pragma unroll
        for (int off = 1; off < 32; off <<= 1) {
            int t = __shfl_up_sync(0xffffffffu, v, off);
            if (lane >= off) v += t;
        }
        if (lane == 31) s_w[wid] = v;
        __syncthreads();
        if (wid == 0) {
            int s = s_w[lane];
            #pragma unroll
            for (int off = 1; off < 32; off <<= 1) {
                int t = __shfl_up_sync(0xffffffffu, s, off);
                if (lane >= off) s += t;
            }
            s_w[lane] = s;
        }
        __syncthreads();
        int res = v + (wid > 0 ? s_w[wid - 1] : 0) + s_carry;
        if (i < n) g_rowptr[i] = res;
        if (i < N_NODES) g_cursor[i] = res;
        __syncthreads();
        if (tid == 1023) s_carry = res;
        __syncthreads();
    }
}
__global__ void k_scatter(const int* __restrict__ src, const int* __restrict__ dst,
                          const int* __restrict__ et) {
    int e = blockIdx.x * blockDim.x + threadIdx.x;
    if (e < N_EDGES) {
        int slot = atomicAdd(&g_cursor[dst[e]], 1);
        g_epack[slot] = src[e] | (et[e] << 20);
    }
}

// ---------------- rel projection, both layers ---------------------------------
__global__ void k_relproj(const float* __restrict__ rel_emb,
                          const float* __restrict__ We,
                          const float* __restrict__ be) {
    int r = blockIdx.x % RNUM, l = blockIdx.x / RNUM;
    int o = threadIdx.x;
    const float* W = We + l * FDIM * FDIM;
    float acc = be[l * FDIM + o];
    #pragma unroll 4
    for (int f = 0; f < FDIM; f++)
        acc += rel_emb[r * FDIM + f] * W[f * FDIM + o];
    g_rel[(l * RNUM + r) * FDIM + o] = acc;
}

// ---------------- prep: convert 6 weight matrices to fp16 ---------------------
__global__ void k_prepw(const float* __restrict__ Wq, const float* __restrict__ Wk,
                        const float* __restrict__ Wv) {
    int i = blockIdx.x * 256 + threadIdx.x;      // 6*16384 elements
    int mat = i >> 14, r = i & 16383;
    int sel = mat % 3, layer = mat / 3;
    const float* W = (sel == 0 ? Wq : sel == 1 ? Wk : Wv) + layer * FDIM * FDIM;
    g_wh[i] = __float2half_rn(W[r]);
}

// ---------------- fused QKV GEMM via HMMA (m16n8k16, fp16 in, fp32 acc) -------
__global__ void __launch_bounds__(256) k_gemm_qkv(const float* __restrict__ Aext, int layer,
                                                  const float* __restrict__ bq,
                                                  const float* __restrict__ bk,
                                                  const float* __restrict__ bv) {
    const float* A = layer ? g_h : Aext;
    extern __shared__ __half sm[];
    __half (*As)[136] = (__half(*)[136])sm;               // [128][136]
    __half (*Bs)[136] = (__half(*)[136])(sm + 128 * 136); // [128][136], [k][n]

    int tid = threadIdx.x, wid = tid >> 5, lane = tid & 31;
    int wm = wid & 3, wn = wid >> 2;
    int rowBase = blockIdx.x * 128;
    unsigned sA = smem_u32(As), sB = smem_u32(Bs);

    #pragma unroll
    for (int t = 0; t < 16; t++) {
        int v = tid + t * 256;
        int r = v >> 5, c4 = v & 31;
        int grow = rowBase + r;
        float4 a = (grow < N_NODES)
            ? *(const float4*)(A + (size_t)grow * FDIM + c4 * 4)
            : make_float4(0.f, 0.f, 0.f, 0.f);
        *(__half2*)&As[r][c4 * 4]     = __floats2half2_rn(a.x, a.y);
        *(__half2*)&As[r][c4 * 4 + 2] = __floats2half2_rn(a.z, a.w);
    }

    unsigned quad = lane >> 3, lr = lane & 7;
    int g = lane >> 2, tg = lane & 3;

    #pragma unroll 1
    for (int sel = 0; sel < 3; sel++) {
        __syncthreads();
        {
            const __half* Wsrc = g_wh + (size_t)(layer * 3 + sel) * 16384;
            #pragma unroll
            for (int t = 0; t < 8; t++) {
                int v = tid + t * 256;
                int r = v >> 4, c8 = v & 15;
                *(uint4*)&Bs[r][c8 * 8] = *(const uint4*)(Wsrc + r * FDIM + c8 * 8);
            }
        }
        __syncthreads();

        float acc[2][8][4];
        #pragma unroll
        for (int i = 0; i < 2; i++)
            #pragma unroll
            for (int j = 0; j < 8; j++)
                #pragma unroll
                for (int c = 0; c < 4; c++) acc[i][j][c] = 0.f;

        #pragma unroll
        for (int ks = 0; ks < 8; ks++) {
            int k0 = ks * 16;
            unsigned af[2][4], bf[4][4];
            #pragma unroll
            for (int i = 0; i < 2; i++) {
                int arow = wm * 32 + i * 16 + ((quad & 1) << 3) + lr;
                int acol = k0 + ((quad >> 1) << 3);
                ldsm4(af[i], sA + (arow * 136 + acol) * 2);
            }
            #pragma unroll
            for (int j2 = 0; j2 < 4; j2++) {
                int brow = k0 + ((quad & 1) << 3) + lr;
                int bcol = wn * 64 + j2 * 16 + ((quad >> 1) << 3);
                ldsm4t(bf[j2], sB + (brow * 136 + bcol) * 2);
            }
            #pragma unroll
            for (int i = 0; i < 2; i++)
                #pragma unroll
                for (int j = 0; j < 8; j++)
                    mma16816(acc[i][j], af[i], &bf[j >> 1][(j & 1) * 2]);
        }

        const float* bias = (sel == 0 ? bq : sel == 1 ? bk : bv) + layer * FDIM;
        #pragma unroll
        for (int i = 0; i < 2; i++) {
            int r0 = rowBase + wm * 32 + i * 16 + g;
            int r1 = r0 + 8;
            #pragma unroll
            for (int j = 0; j < 8; j++) {
                int col = wn * 64 + j * 8 + tg * 2;
                float2 b2 = *(const float2*)(bias + col);
                float d0 = acc[i][j][0] + b2.x, d1 = acc[i][j][1] + b2.y;
                float d2 = acc[i][j][2] + b2.x, d3 = acc[i][j][3] + b2.y;
                if (sel == 0) {
                    if (r0 < N_NODES) *(float2*)(g_q + (size_t)r0 * FDIM + col) = make_float2(d0, d1);
                    if (r1 < N_NODES) *(float2*)(g_q + (size_t)r1 * FDIM + col) = make_float2(d2, d3);
                } else {
                    int off = (sel == 1) ? 0 : FDIM;
                    if (r0 < N_NODES)
                        *(__half2*)(g_kvh + (size_t)r0 * 2 * FDIM + off + col) = __floats2half2_rn(d0, d1);
                    if (r1 < N_NODES)
                        *(__half2*)(g_kvh + (size_t)r1 * 2 * FDIM + off + col) = __floats2half2_rn(d2, d3);
                }
            }
        }
    }
}

// ---------------- fused attention: warp per dst node, 8 lanes per head --------
// No online max (softmax shift-invariance; scores bounded). 2-edge software
// pipeline: two independent k/v/rel register sets and score chains in flight.
template <int LAYER>
__global__ void __launch_bounds__(256) k_attn(const float* __restrict__ inputs,
                                              const float* __restrict__ Wout,
                                              const float* __restrict__ bout,
                                              const float* __restrict__ cent,
                                              const float* __restrict__ gamma,
                                              const float* __restrict__ beta,
                                              float* __restrict__ out) {
    __shared__ float4 s_rel[RNUM * 32];
    {
        const float4* rel4 = (const float4*)(g_rel + LAYER * RNUM * FDIM);
        for (int i = threadIdx.x; i < RNUM * 32; i += 256) s_rel[i] = rel4[i];
    }
    __syncthreads();

    int gw = (blockIdx.x * 256 + threadIdx.x) >> 5;
    int lane = threadIdx.x & 31;
    if (gw >= N_NODES) return;

    const float* hin = LAYER ? g_h : inputs;
    const uint2* kvp = (const uint2*)g_kvh;     // 4 halves per uint2; 64 per node
    int idx = gw * 32 + lane;

    float4 qr = ((const float4*)g_q)[idx];
    qr.x *= SCALE2F; qr.y *= SCALE2F; qr.z *= SCALE2F; qr.w *= SCALE2F;
    float ss = 0.f;
    float4 acc = make_float4(0.f, 0.f, 0.f, 0.f);

    int e0 = g_rowptr[gw], e1 = g_rowptr[gw + 1];

    uint2 ka, va, kb, vb;
    float4 ra, rb;
    if (e0 < e1) {
        int p = g_epack[e0];
        int si = (p & 0xFFFFF) * 64 + lane;
        ka = kvp[si]; va = kvp[si + 32]; ra = s_rel[(p >> 20) * 32 + lane];
    }
    if (e0 + 1 < e1) {
        int p = g_epack[e0 + 1];
        int si = (p & 0xFFFFF) * 64 + lane;
        kb = kvp[si]; vb = kvp[si + 32]; rb = s_rel[(p >> 20) * 32 + lane];
    }

    int e = e0;
    for (; e + 1 < e1; e += 2) {
        // slot A: compute edge e, prefetch e+2
        uint2 kr0 = ka, vr0 = va; float4 rel0 = ra;
        if (e + 2 < e1) {
            int p = g_epack[e + 2];
            int si = (p & 0xFFFFF) * 64 + lane;
            ka = kvp[si]; va = kvp[si + 32]; ra = s_rel[(p >> 20) * 32 + lane];
        }
        // slot B: compute edge e+1, prefetch e+3
        uint2 kr1 = kb, vr1 = vb; float4 rel1 = rb;
        if (e + 3 < e1) {
            int p = g_epack[e + 3];
            int si = (p & 0xFFFFF) * 64 + lane;
            kb = kvp[si]; vb = kvp[si + 32]; rb = s_rel[(p >> 20) * 32 + lane];
        }

        float2 k01a = __half22float2(*(__half2*)&kr0.x);
        float2 k23a = __half22float2(*(__half2*)&kr0.y);
        float2 k01b = __half22float2(*(__half2*)&kr1.x);
        float2 k23b = __half22float2(*(__half2*)&kr1.y);
        float pa = qr.x * (k01a.x + rel0.x) + qr.y * (k01a.y + rel0.y)
                 + qr.z * (k23a.x + rel0.z) + qr.w * (k23a.y + rel0.w);
        float pb = qr.x * (k01b.x + rel1.x) + qr.y * (k01b.y + rel1.y)
                 + qr.z * (k23b.x + rel1.z) + qr.w * (k23b.y + rel1.w);
        pa += __shfl_xor_sync(0xffffffffu, pa, 4);
        pb += __shfl_xor_sync(0xffffffffu, pb, 4);
        pa += __shfl_xor_sync(0xffffffffu, pa, 2);
        pb += __shfl_xor_sync(0xffffffffu, pb, 2);
        pa += __shfl_xor_sync(0xffffffffu, pa, 1);
        pb += __shfl_xor_sync(0xffffffffu, pb, 1);
        float wa = exp2f(pa);
        float wb = exp2f(pb);
        float2 v01a = __half22float2(*(__half2*)&vr0.x);
        float2 v23a = __half22float2(*(__half2*)&vr0.y);
        float2 v01b = __half22float2(*(__half2*)&vr1.x);
        float2 v23b = __half22float2(*(__half2*)&vr1.y);
        ss += wa;
        acc.x += wa * (v01a.x + rel0.x);
        acc.y += wa * (v01a.y + rel0.y);
        acc.z += wa * (v23a.x + rel0.z);
        acc.w += wa * (v23a.y + rel0.w);
        ss += wb;
        acc.x += wb * (v01b.x + rel1.x);
        acc.y += wb * (v01b.y + rel1.y);
        acc.z += wb * (v23b.x + rel1.z);
        acc.w += wb * (v23b.y + rel1.w);
    }
    if (e < e1) {
        float2 k01 = __half22float2(*(__half2*)&ka.x);
        float2 k23 = __half22float2(*(__half2*)&ka.y);
        float pr = qr.x * (k01.x + ra.x) + qr.y * (k01.y + ra.y)
                 + qr.z * (k23.x + ra.z) + qr.w * (k23.y + ra.w);
        pr += __shfl_xor_sync(0xffffffffu, pr, 4);
        pr += __shfl_xor_sync(0xffffffffu, pr, 2);
        pr += __shfl_xor_sync(0xffffffffu, pr, 1);
        float w = exp2f(pr);
        float2 v01 = __half22float2(*(__half2*)&va.x);
        float2 v23 = __half22float2(*(__half2*)&va.y);
        ss += w;
        acc.x += w * (v01.x + ra.x);
        acc.y += w * (v01.y + ra.y);
        acc.z += w * (v23.x + ra.z);
        acc.w += w * (v23.y + ra.w);
    }

    float inv = 1.f / (ss + 1e-9f);
    float4 hi = ((const float4*)hin)[idx];
    float4 x;
    x.x = acc.x * inv + hi.x;
    x.y = acc.y * inv + hi.y;
    x.z = acc.z * inv + hi.z;
    x.w = acc.w * inv + hi.w;
    x.x = (x.x > 0.f) ? x.x : (__expf(x.x) - 1.f);
    x.y = (x.y > 0.f) ? x.y : (__expf(x.y) - 1.f);
    x.z = (x.z > 0.f) ? x.z : (__expf(x.z) - 1.f);
    x.w = (x.w > 0.f) ? x.w : (__expf(x.w) - 1.f);

    if (LAYER == 0) {
        ((float4*)g_h)[idx] = x;
    } else {
        float4 w4 = ((const float4*)Wout)[lane];
        float p = x.x * w4.x + x.y * w4.y + x.z * w4.z + x.w * w4.w;
        p += __shfl_xor_sync(0xffffffffu, p, 16);
        p += __shfl_xor_sync(0xffffffffu, p, 8);
        p += __shfl_xor_sync(0xffffffffu, p, 4);
        p += __shfl_xor_sync(0xffffffffu, p, 2);
        p += __shfl_xor_sync(0xffffffffu, p, 1);
        if (lane == 0) {
            float lg = p + bout[0];
            float sc = cent[gw] * gamma[0] + beta[0];
            float r = sc * lg;
            out[gw] = (r > 0.f) ? r : 0.f;
        }
    }
}

// ---------------- launch ------------------------------------------------------
extern "C" void kernel_launch(void* const* d_in, const int* in_sizes, int n_in,
                              void* d_out, int out_size) {
    const float* inputs  = (const float*)d_in[0];
    const int*   et      = (const int*)d_in[1];
    const int*   src     = (const int*)d_in[2];
    const int*   dst     = (const int*)d_in[3];
    const float* cent    = (const float*)d_in[4];
    const float* rel_emb = (const float*)d_in[5];
    const float* Wq      = (const float*)d_in[6];
    const float* bq      = (const float*)d_in[7];
    const float* Wk      = (const float*)d_in[8];
    const float* bk      = (const float*)d_in[9];
    const float* Wv      = (const float*)d_in[10];
    const float* bv      = (const float*)d_in[11];
    const float* We      = (const float*)d_in[12];
    const float* be      = (const float*)d_in[13];
    const float* Wout    = (const float*)d_in[14];
    const float* bout    = (const float*)d_in[15];
    const float* gamma   = (const float*)d_in[16];
    const float* beta    = (const float*)d_in[17];
    float* out = (float*)d_out;

    const int GEMM_SMEM = 2 * 128 * 136 * 2;   // 69632 bytes

    static cudaStream_t s1 = nullptr, s2 = nullptr;
    static cudaEvent_t ev_fork = nullptr, ev_prep = nullptr, ev_rel = nullptr, ev_csr = nullptr;
    if (s1 == nullptr) {
        cudaStreamCreateWithFlags(&s1, cudaStreamNonBlocking);
        cudaStreamCreateWithFlags(&s2, cudaStreamNonBlocking);
        cudaEventCreateWithFlags(&ev_fork, cudaEventDisableTiming);
        cudaEventCreateWithFlags(&ev_prep, cudaEventDisableTiming);
        cudaEventCreateWithFlags(&ev_rel, cudaEventDisableTiming);
        cudaEventCreateWithFlags(&ev_csr, cudaEventDisableTiming);
        cudaFuncSetAttribute(k_gemm_qkv, cudaFuncAttributeMaxDynamicSharedMemorySize, GEMM_SMEM);
    }

    cudaEventRecord(ev_fork, 0);

    // s1: W fp16 conversion, then rel projections
    cudaStreamWaitEvent(s1, ev_fork, 0);
    k_prepw<<<(6 * FDIM * FDIM) / 256, 256, 0, s1>>>(Wq, Wk, Wv);
    cudaEventRecord(ev_prep, s1);
    k_relproj<<<NLAYER * RNUM, FDIM, 0, s1>>>(rel_emb, We, be);
    cudaEventRecord(ev_rel, s1);

    // s2: CSR build
    cudaStreamWaitEvent(s2, ev_fork, 0);
    k_zero_rowptr<<<(N_NODES + 256) / 256, 256, 0, s2>>>();
    k_hist<<<(N_EDGES + 255) / 256, 256, 0, s2>>>(dst);
    k_scan<<<1, 1024, 0, s2>>>();
    k_scatter<<<(N_EDGES + 255) / 256, 256, 0, s2>>>(src, dst, et);
    cudaEventRecord(ev_csr, s2);

    int attn_blocks = (N_NODES * 32 + 255) / 256;

    // layer 0
    cudaStreamWaitEvent(0, ev_prep, 0);
    k_gemm_qkv<<<NTILES, 256, GEMM_SMEM>>>(inputs, 0, bq, bk, bv);
    cudaStreamWaitEvent(0, ev_csr, 0);
    cudaStreamWaitEvent(0, ev_rel, 0);
    k_attn<0><<<attn_blocks, 256>>>(inputs, Wout, bout, cent, gamma, beta, out);

    // layer 1 (+ fused output head)
    k_gemm_qkv<<<NTILES, 256, GEMM_SMEM>>>(inputs, 1, bq, bk, bv);
    k_attn<1><<<attn_blocks, 256>>>(inputs, Wout, bout, cent, gamma, beta, out);
}